// round 3
// baseline (speedup 1.0000x reference)
#include <cuda_runtime.h>
#include <cuda_bf16.h>
#include <cstdint>

// ROIAlign, OUT=15x15, SCALE=1/16, SR=2
// x: [2,256,64,64] f32; boxes: [512,4] f32; batch_idx: [512] i32
// out: [512,256,15,15] f32

#define HH 64
#define WW 64
#define CC 256
#define OUT_HW 15
#define NBOX 512

// channels-last scratch: [2,64,64,256] f32 = 8MB
__device__ float g_xt[2 * HH * WW * CC];

// ---------------------------------------------------------------------------
// Transpose [B,C,H*W] -> [B,H*W,C] via 32x32 smem tiles
// ---------------------------------------------------------------------------
__global__ __launch_bounds__(256) void transpose_kernel(const float* __restrict__ x) {
    __shared__ float tile[32][33];
    int b   = blockIdx.z;
    int hw0 = blockIdx.x * 32;  // 4096/32 = 128 blocks
    int c0  = blockIdx.y * 32;  // 256/32  = 8 blocks
    const float* src = x + ((size_t)b * CC) * (HH * WW);
    // read: coalesced along hw
    #pragma unroll
    for (int i = threadIdx.y; i < 32; i += 8)
        tile[i][threadIdx.x] = src[(size_t)(c0 + i) * (HH * WW) + hw0 + threadIdx.x];
    __syncthreads();
    // write: coalesced along c
    float* dst = g_xt + (size_t)b * (HH * WW) * CC;
    #pragma unroll
    for (int i = threadIdx.y; i < 32; i += 8)
        dst[(size_t)(hw0 + i) * CC + c0 + threadIdx.x] = tile[threadIdx.x][i];
}

// ---------------------------------------------------------------------------
// Main ROIAlign kernel. Grid: (15, 512) = (h, box). Block: 128 threads,
// thread t owns channels 2t, 2t+1 (float2 loads from channels-last scratch).
//
// Precompute (threads 0..15): per-bin deduped x corner lists with combined
// (bilinear * subsample-mean) weights, and the row-shared y corner list.
// Weight separability: sum over (sy,sx) samples of wy*wx factorizes into
// (sum_y wy) * (sum_x wx), so <=3 x-corners times <=3 y-corners per bin.
// ---------------------------------------------------------------------------
__global__ __launch_bounds__(128) void roi_kernel(const float* __restrict__ boxes,
                                                  const int* __restrict__ batch_idx,
                                                  float* __restrict__ out) {
    const int h = blockIdx.x;
    const int n = blockIdx.y;

    __shared__ int   s_ny;
    __shared__ int   s_yoff[4];
    __shared__ float s_ywt[4];
    __shared__ int   s_nx[OUT_HW];
    __shared__ int   s_xoff[OUT_HW][4];
    __shared__ float s_xwt[OUT_HW][4];

    const int tid = threadIdx.x;

    if (tid < 16) {
        const float x1 = boxes[n * 4 + 0] * 0.0625f;
        const float y1 = boxes[n * 4 + 1] * 0.0625f;
        const float x2 = boxes[n * 4 + 2] * 0.0625f;
        const float y2 = boxes[n * 4 + 3] * 0.0625f;
        const float roi_w = fmaxf(x2 - x1, 1.0f);
        const float roi_h = fmaxf(y2 - y1, 1.0f);
        const float bin_w = roi_w * (1.0f / OUT_HW);
        const float bin_h = roi_h * (1.0f / OUT_HW);

        if (tid < OUT_HW) {
            // per-bin x corner list (deduped across the 2 x-subsamples)
            const int w = tid;
            int   idx[4];
            float wt[4];
            int   cnt = 0;
            #pragma unroll
            for (int sx = 0; sx < 2; sx++) {
                const int   j = w * 2 + sx;
                float p = x1 + ((float)j + 0.5f) * 0.5f * bin_w;
                const float v = (p >= -1.0f && p <= (float)WW) ? 0.5f : 0.0f;  // validity * subsample mean(0.5)
                p = fminf(fmaxf(p, 0.0f), (float)(WW - 1));
                int lo = (int)floorf(p);
                if (lo > WW - 1) lo = WW - 1;
                const int   hi = min(lo + 1, WW - 1);
                const float f  = p - (float)lo;
                int   ci[2] = { lo, hi };
                float cw[2] = { (1.0f - f) * v, f * v };
                #pragma unroll
                for (int k = 0; k < 2; k++) {
                    int m;
                    for (m = 0; m < cnt; m++)
                        if (idx[m] == ci[k]) { wt[m] += cw[k]; break; }
                    if (m == cnt) { idx[cnt] = ci[k]; wt[cnt] = cw[k]; cnt++; }
                }
            }
            s_nx[w] = cnt;
            for (int m = 0; m < cnt; m++) {
                s_xoff[w][m] = idx[m] * CC;
                s_xwt[w][m]  = wt[m];
            }
        } else {
            // tid == 15: row-shared y corner list
            const int b = batch_idx[n];
            int   idx[4];
            float wt[4];
            int   cnt = 0;
            #pragma unroll
            for (int sy = 0; sy < 2; sy++) {
                const int   ky = h * 2 + sy;
                float p = y1 + ((float)ky + 0.5f) * 0.5f * bin_h;
                const float v = (p >= -1.0f && p <= (float)HH) ? 0.5f : 0.0f;
                p = fminf(fmaxf(p, 0.0f), (float)(HH - 1));
                int lo = (int)floorf(p);
                if (lo > HH - 1) lo = HH - 1;
                const int   hi = min(lo + 1, HH - 1);
                const float f  = p - (float)lo;
                int   ci[2] = { lo, hi };
                float cw[2] = { (1.0f - f) * v, f * v };
                #pragma unroll
                for (int k = 0; k < 2; k++) {
                    int m;
                    for (m = 0; m < cnt; m++)
                        if (idx[m] == ci[k]) { wt[m] += cw[k]; break; }
                    if (m == cnt) { idx[cnt] = ci[k]; wt[cnt] = cw[k]; cnt++; }
                }
            }
            s_ny = cnt;
            for (int m = 0; m < cnt; m++) {
                s_yoff[m] = (b * (HH * WW) + idx[m] * WW) * CC;
                s_ywt[m]  = wt[m];
            }
        }
    }
    __syncthreads();

    const int c0 = tid * 2;

    float res0[OUT_HW];
    float res1[OUT_HW];
    #pragma unroll
    for (int w = 0; w < OUT_HW; w++) { res0[w] = 0.0f; res1[w] = 0.0f; }

    const int ny = s_ny;
    for (int yi = 0; yi < ny; yi++) {
        const float* rowp = g_xt + s_yoff[yi] + c0;
        const float  wy   = s_ywt[yi];
        #pragma unroll
        for (int w = 0; w < OUT_HW; w++) {
            const int nx = s_nx[w];
            float acc0 = 0.0f, acc1 = 0.0f;
            for (int xi = 0; xi < nx; xi++) {
                const float  ww = s_xwt[w][xi];
                const float2 v  = __ldg(reinterpret_cast<const float2*>(rowp + s_xoff[w][xi]));
                acc0 += ww * v.x;
                acc1 += ww * v.y;
            }
            res0[w] += wy * acc0;
            res1[w] += wy * acc1;
        }
    }

    // out[n, c, h, w]: thread writes 15 contiguous floats per channel
    float* o0 = out + (size_t)n * CC * (OUT_HW * OUT_HW) + (size_t)c0 * (OUT_HW * OUT_HW) + h * OUT_HW;
    float* o1 = o0 + (OUT_HW * OUT_HW);
    #pragma unroll
    for (int w = 0; w < OUT_HW; w++) o0[w] = res0[w];
    #pragma unroll
    for (int w = 0; w < OUT_HW; w++) o1[w] = res1[w];
}

// ---------------------------------------------------------------------------
extern "C" void kernel_launch(void* const* d_in, const int* in_sizes, int n_in,
                              void* d_out, int out_size) {
    const float* x     = (const float*)d_in[0];
    const float* boxes = (const float*)d_in[1];
    const int*   bidx  = (const int*)d_in[2];
    float*       out   = (float*)d_out;

    (void)in_sizes; (void)n_in; (void)out_size;

    dim3 tb(32, 8);
    dim3 tg((HH * WW) / 32, CC / 32, 2);
    transpose_kernel<<<tg, tb>>>(x);

    dim3 rg(OUT_HW, NBOX);
    roi_kernel<<<rg, 128>>>(boxes, bidx, out);
}

// round 5
// speedup vs baseline: 2.7386x; 2.7386x over previous
#include <cuda_runtime.h>
#include <cuda_bf16.h>
#include <cstdint>

// ROIAlign, OUT=15x15, SCALE=1/16, SR=2
// x: [2,256,64,64] f32; boxes: [512,4] f32; batch_idx: [512] i32
// out: [512,256,15,15] f32
//
// Strategy: channels-last transpose into 8MB scratch, then box-per-block
// ROI kernel: the whole sampled footprint of a box is <=12x12 feature
// pixels (roi_w,roi_h <= 10), so load a 12x12x64ch patch into smem once
// and compute all 225 bins from smem. 9x less L2 read traffic than the
// row-refetch version.

#define HH 64
#define WW 64
#define CC 256
#define OUT_HW 15
#define NBOX 512
#define PW 12
#define PH 12
#define CPAD 17  // float4 stride per patch position (16 + 1 pad: kills px bank conflicts)

// channels-last scratch: [2,64,64,256] f32 = 8MB
__device__ float g_xt[2 * HH * WW * CC];

// ---------------------------------------------------------------------------
// Transpose [B,C,H*W] -> [B,H*W,C] via 32x32 smem tiles
// ---------------------------------------------------------------------------
__global__ __launch_bounds__(256) void transpose_kernel(const float* __restrict__ x) {
    __shared__ float tile[32][33];
    int b   = blockIdx.z;
    int hw0 = blockIdx.x * 32;
    int c0  = blockIdx.y * 32;
    const float* src = x + ((size_t)b * CC) * (HH * WW);
    #pragma unroll
    for (int i = threadIdx.y; i < 32; i += 8)
        tile[i][threadIdx.x] = src[(size_t)(c0 + i) * (HH * WW) + hw0 + threadIdx.x];
    __syncthreads();
    float* dst = g_xt + (size_t)b * (HH * WW) * CC;
    #pragma unroll
    for (int i = threadIdx.y; i < 32; i += 8)
        dst[(size_t)(hw0 + i) * CC + c0 + threadIdx.x] = tile[threadIdx.x][i];
}

// ---------------------------------------------------------------------------
// Axis corner-list builder: dedup the <=4 bilinear corners of the 2
// subsamples into <=3 (index, weight) pairs. v folds validity * 0.5 mean.
// ---------------------------------------------------------------------------
__device__ __forceinline__ void axis_bin(float a1, float bin, int bin_i, int base,
                                         int size, int* o_idx, float* o_wt, int* o_n) {
    int   idx[3];
    float wt[3];
    int   cnt = 0;
    #pragma unroll
    for (int s = 0; s < 2; s++) {
        float p = a1 + ((float)(bin_i * 2 + s) + 0.5f) * 0.5f * bin;
        const float v = (p >= -1.0f && p <= (float)size) ? 0.5f : 0.0f;
        p = fminf(fmaxf(p, 0.0f), (float)(size - 1));
        int lo = (int)floorf(p);
        if (lo > size - 1) lo = size - 1;
        const int   hi = min(lo + 1, size - 1);
        const float f  = p - (float)lo;
        int   ci[2] = { lo - base, hi - base };
        float cw[2] = { (1.0f - f) * v, f * v };
        #pragma unroll
        for (int k = 0; k < 2; k++) {
            int m;
            for (m = 0; m < cnt; m++)
                if (idx[m] == ci[k]) { wt[m] += cw[k]; break; }
            if (m == cnt && cnt < 3) { idx[cnt] = ci[k]; wt[cnt] = cw[k]; cnt++; }
        }
    }
    *o_n = cnt;
    for (int m = 0; m < cnt; m++) { o_idx[m] = idx[m]; o_wt[m] = wt[m]; }
}

// ---------------------------------------------------------------------------
// ROI kernel: grid (4 chunk, 512 box), 256 threads. Thread tid<225 owns
// output bin (h,w) = (tid/15, tid%15) across 64 channels (chunk slice).
// ---------------------------------------------------------------------------
__global__ __launch_bounds__(256) void roi_kernel(const float* __restrict__ boxes,
                                                  const int* __restrict__ batch_idx,
                                                  float* __restrict__ out) {
    const int chunk = blockIdx.x;
    const int n     = blockIdx.y;
    const int tid   = threadIdx.x;

    __shared__ float4 patch[PH * PW * CPAD];       // 39168 B
    __shared__ int    s_xn[OUT_HW];
    __shared__ int    s_xc[OUT_HW][3];
    __shared__ float  s_xw[OUT_HW][3];
    __shared__ int    s_yn[OUT_HW];
    __shared__ int    s_yr[OUT_HW][3];
    __shared__ float  s_yw[OUT_HW][3];

    // ---- every thread computes box geometry (broadcast loads, cheap) ----
    const float bx1 = boxes[n * 4 + 0] * 0.0625f;
    const float by1 = boxes[n * 4 + 1] * 0.0625f;
    const float bx2 = boxes[n * 4 + 2] * 0.0625f;
    const float by2 = boxes[n * 4 + 3] * 0.0625f;
    const float bin_w = fmaxf(bx2 - bx1, 1.0f) * (1.0f / OUT_HW);
    const float bin_h = fmaxf(by2 - by1, 1.0f) * (1.0f / OUT_HW);
    const int   b     = batch_idx[n];

    // min corner = floor(clip(first sample)) on each axis
    float p0x = fminf(fmaxf(bx1 + 0.25f * bin_w, 0.0f), (float)(WW - 1));
    float p0y = fminf(fmaxf(by1 + 0.25f * bin_h, 0.0f), (float)(HH - 1));
    const int x_base = (int)floorf(p0x);
    const int y_base = (int)floorf(p0y);

    // ---- per-bin corner lists (threads 0..14: x axis; 32..46: y axis) ----
    if (tid < OUT_HW) {
        int idx[3]; float wt[3]; int cnt;
        axis_bin(bx1, bin_w, tid, x_base, WW, idx, wt, &cnt);
        s_xn[tid] = cnt;
        for (int m = 0; m < cnt; m++) { s_xc[tid][m] = idx[m]; s_xw[tid][m] = wt[m]; }
    } else if (tid >= 32 && tid < 32 + OUT_HW) {
        const int h = tid - 32;
        int idx[3]; float wt[3]; int cnt;
        axis_bin(by1, bin_h, h, y_base, HH, idx, wt, &cnt);
        s_yn[h] = cnt;
        for (int m = 0; m < cnt; m++) { s_yr[h][m] = idx[m]; s_yw[h][m] = wt[m]; }
    }

    // ---- patch load: 12x12 positions x 16 float4 (64 ch) ----
    {
        const float* src = g_xt + (size_t)b * (HH * WW * CC) + chunk * 64;
        #pragma unroll
        for (int i = tid; i < PH * PW * 16; i += 256) {
            const int pos = i >> 4;
            const int c4  = i & 15;
            const int py  = pos / PW;
            const int px  = pos - py * PW;
            const int y   = min(y_base + py, HH - 1);
            const int x   = min(x_base + px, WW - 1);
            const float4 v = *reinterpret_cast<const float4*>(src + ((size_t)y * WW + x) * CC + c4 * 4);
            patch[pos * CPAD + c4] = v;
        }
    }
    __syncthreads();

    if (tid >= OUT_HW * OUT_HW) return;

    const int h = tid / OUT_HW;
    const int w = tid - h * OUT_HW;

    // combined corner list for this bin (<=9 entries, kept in registers)
    int   offs[9];
    float wts[9];
    const int ny = s_yn[h];
    const int nx = s_xn[w];
    const int nc = ny * nx;
    {
        int k = 0;
        #pragma unroll
        for (int yi = 0; yi < 3; yi++) {
            if (yi < ny) {
                const int   ro = s_yr[h][yi] * PW;
                const float yw = s_yw[h][yi];
                #pragma unroll
                for (int xi = 0; xi < 3; xi++) {
                    if (xi < nx) {
                        offs[k] = (ro + s_xc[w][xi]) * CPAD;
                        wts[k]  = yw * s_xw[w][xi];
                        k++;
                    }
                }
            }
        }
    }

    float* obase = out + ((size_t)n * CC + chunk * 64) * (OUT_HW * OUT_HW) + tid;

    #pragma unroll
    for (int cg = 0; cg < 4; cg++) {
        float4 a0 = {0.f, 0.f, 0.f, 0.f};
        float4 a1 = {0.f, 0.f, 0.f, 0.f};
        float4 a2 = {0.f, 0.f, 0.f, 0.f};
        float4 a3 = {0.f, 0.f, 0.f, 0.f};
        #pragma unroll
        for (int i = 0; i < 9; i++) {
            if (i < nc) {
                const float4* p = &patch[offs[i] + cg * 4];
                const float   g = wts[i];
                float4 v;
                v = p[0]; a0.x = fmaf(g, v.x, a0.x); a0.y = fmaf(g, v.y, a0.y);
                          a0.z = fmaf(g, v.z, a0.z); a0.w = fmaf(g, v.w, a0.w);
                v = p[1]; a1.x = fmaf(g, v.x, a1.x); a1.y = fmaf(g, v.y, a1.y);
                          a1.z = fmaf(g, v.z, a1.z); a1.w = fmaf(g, v.w, a1.w);
                v = p[2]; a2.x = fmaf(g, v.x, a2.x); a2.y = fmaf(g, v.y, a2.y);
                          a2.z = fmaf(g, v.z, a2.z); a2.w = fmaf(g, v.w, a2.w);
                v = p[3]; a3.x = fmaf(g, v.x, a3.x); a3.y = fmaf(g, v.y, a3.y);
                          a3.z = fmaf(g, v.z, a3.z); a3.w = fmaf(g, v.w, a3.w);
            }
        }
        // channel of a_q component k = chunk*64 + cg*16 + q*4 + k
        float* o = obase + (size_t)(cg * 16) * (OUT_HW * OUT_HW);
        const int S = OUT_HW * OUT_HW;
        o[0 * S] = a0.x; o[1 * S]  = a0.y; o[2 * S]  = a0.z; o[3 * S]  = a0.w;
        o[4 * S] = a1.x; o[5 * S]  = a1.y; o[6 * S]  = a1.z; o[7 * S]  = a1.w;
        o[8 * S] = a2.x; o[9 * S]  = a2.y; o[10 * S] = a2.z; o[11 * S] = a2.w;
        o[12 * S] = a3.x; o[13 * S] = a3.y; o[14 * S] = a3.z; o[15 * S] = a3.w;
    }
}

// ---------------------------------------------------------------------------
extern "C" void kernel_launch(void* const* d_in, const int* in_sizes, int n_in,
                              void* d_out, int out_size) {
    const float* x     = (const float*)d_in[0];
    const float* boxes = (const float*)d_in[1];
    const int*   bidx  = (const int*)d_in[2];
    float*       out   = (float*)d_out;

    (void)in_sizes; (void)n_in; (void)out_size;

    dim3 tb(32, 8);
    dim3 tg((HH * WW) / 32, CC / 32, 2);
    transpose_kernel<<<tg, tb>>>(x);

    dim3 rg(4, NBOX);
    roi_kernel<<<rg, 256>>>(boxes, bidx, out);
}

// round 6
// speedup vs baseline: 3.2458x; 1.1852x over previous
#include <cuda_runtime.h>
#include <cuda_bf16.h>
#include <cstdint>

// ROIAlign, OUT=15x15, SCALE=1/16, SR=2
// x: [2,256,64,64] f32; boxes: [512,4] f32; batch_idx: [512] i32
// out: [512,256,15,15] f32
//
// v3: channels-last transpose -> per-(box,chunk) block:
//   patch[12x12][64ch] smem load (once), then SEPARABLE two-stage:
//   stage1: vrow[h][x][c] = sum_yi wy * patch[yr][x][c]   (y-combine)
//   stage2: out[h][w][c]  = sum_xi wx * vrow[h][xc][c]    (x-combine)
//   vrow uses XOR bank swizzle (c4 ^ (pos&7)) -> conflict-free STS and
//   well-spread stage2 LDS. Cuts smem read bytes ~2x vs one-pass 9-corner.

#define HH 64
#define WW 64
#define CC 256
#define OUT_HW 15
#define NBOX 512
#define PW 12
#define PH 12

#define PATCH_F4 (PH * PW * 16)          // 2304 float4 = 36864 B
#define VROW_F4  (OUT_HW * PW * 16)      // 2880 float4 = 46080 B
#define SMEM_DYN ((PATCH_F4 + VROW_F4) * 16)

// vrow index with XOR swizzle: pos in [0,180), c4 in [0,16)
#define VIDX(pos, c4) (((pos) << 4) + ((c4) ^ ((pos) & 7)))

// channels-last scratch: [2,64,64,256] f32 = 8MB
__device__ float g_xt[2 * HH * WW * CC];

// ---------------------------------------------------------------------------
// Transpose [B,C,H*W] -> [B,H*W,C] via 32x32 smem tiles
// ---------------------------------------------------------------------------
__global__ __launch_bounds__(256) void transpose_kernel(const float* __restrict__ x) {
    __shared__ float tile[32][33];
    int b   = blockIdx.z;
    int hw0 = blockIdx.x * 32;
    int c0  = blockIdx.y * 32;
    const float* src = x + ((size_t)b * CC) * (HH * WW);
    #pragma unroll
    for (int i = threadIdx.y; i < 32; i += 8)
        tile[i][threadIdx.x] = src[(size_t)(c0 + i) * (HH * WW) + hw0 + threadIdx.x];
    __syncthreads();
    float* dst = g_xt + (size_t)b * (HH * WW) * CC;
    #pragma unroll
    for (int i = threadIdx.y; i < 32; i += 8)
        dst[(size_t)(hw0 + i) * CC + c0 + threadIdx.x] = tile[threadIdx.x][i];
}

// ---------------------------------------------------------------------------
// Axis corner-list builder: dedup the <=4 bilinear corners of the 2
// subsamples into <=3 (relative index, weight) pairs. v = validity * 0.5.
// ---------------------------------------------------------------------------
__device__ __forceinline__ void axis_bin(float a1, float bin, int bin_i, int base,
                                         int size, int* o_idx, float* o_wt, int* o_n) {
    int   idx[3];
    float wt[3];
    int   cnt = 0;
    #pragma unroll
    for (int s = 0; s < 2; s++) {
        float p = a1 + ((float)(bin_i * 2 + s) + 0.5f) * 0.5f * bin;
        const float v = (p >= -1.0f && p <= (float)size) ? 0.5f : 0.0f;
        p = fminf(fmaxf(p, 0.0f), (float)(size - 1));
        int lo = (int)floorf(p);
        if (lo > size - 1) lo = size - 1;
        const int   hi = min(lo + 1, size - 1);
        const float f  = p - (float)lo;
        int   ci[2] = { lo - base, hi - base };
        float cw[2] = { (1.0f - f) * v, f * v };
        #pragma unroll
        for (int k = 0; k < 2; k++) {
            int m;
            for (m = 0; m < cnt; m++)
                if (idx[m] == ci[k]) { wt[m] += cw[k]; break; }
            if (m == cnt && cnt < 3) { idx[cnt] = ci[k]; wt[cnt] = cw[k]; cnt++; }
        }
    }
    *o_n = cnt;
    for (int m = 0; m < cnt; m++) { o_idx[m] = idx[m]; o_wt[m] = wt[m]; }
}

// ---------------------------------------------------------------------------
// ROI kernel: grid (4 chunk, 512 box), 256 threads.
// ---------------------------------------------------------------------------
__global__ __launch_bounds__(256) void roi_kernel(const float* __restrict__ boxes,
                                                  const int* __restrict__ batch_idx,
                                                  float* __restrict__ out) {
    extern __shared__ float4 dyn[];
    float4* patch = dyn;              // [ppos 0..143][c4 0..15]
    float4* vrow  = dyn + PATCH_F4;   // swizzled [pos 0..179][c4 0..15]

    __shared__ int    s_xn[OUT_HW];
    __shared__ int    s_xc[OUT_HW][3];
    __shared__ float  s_xw[OUT_HW][3];
    __shared__ int    s_yn[OUT_HW];
    __shared__ int    s_yr[OUT_HW][3];
    __shared__ float  s_yw[OUT_HW][3];

    const int chunk = blockIdx.x;
    const int n     = blockIdx.y;
    const int tid   = threadIdx.x;

    // ---- box geometry (broadcast loads) ----
    const float bx1 = boxes[n * 4 + 0] * 0.0625f;
    const float by1 = boxes[n * 4 + 1] * 0.0625f;
    const float bx2 = boxes[n * 4 + 2] * 0.0625f;
    const float by2 = boxes[n * 4 + 3] * 0.0625f;
    const float bin_w = fmaxf(bx2 - bx1, 1.0f) * (1.0f / OUT_HW);
    const float bin_h = fmaxf(by2 - by1, 1.0f) * (1.0f / OUT_HW);
    const int   b     = batch_idx[n];

    float p0x = fminf(fmaxf(bx1 + 0.25f * bin_w, 0.0f), (float)(WW - 1));
    float p0y = fminf(fmaxf(by1 + 0.25f * bin_h, 0.0f), (float)(HH - 1));
    const int x_base = (int)floorf(p0x);
    const int y_base = (int)floorf(p0y);

    // ---- per-bin axis corner lists ----
    if (tid < OUT_HW) {
        int idx[3]; float wt[3]; int cnt;
        axis_bin(bx1, bin_w, tid, x_base, WW, idx, wt, &cnt);
        s_xn[tid] = cnt;
        for (int m = 0; m < cnt; m++) { s_xc[tid][m] = idx[m]; s_xw[tid][m] = wt[m]; }
    } else if (tid >= 32 && tid < 32 + OUT_HW) {
        const int h = tid - 32;
        int idx[3]; float wt[3]; int cnt;
        axis_bin(by1, bin_h, h, y_base, HH, idx, wt, &cnt);
        s_yn[h] = cnt;
        for (int m = 0; m < cnt; m++) { s_yr[h][m] = idx[m]; s_yw[h][m] = wt[m]; }
    }

    // ---- patch load: 144 positions x 16 float4 (64 ch), coalesced ----
    {
        const float* src = g_xt + (size_t)b * (HH * WW * CC) + chunk * 64;
        #pragma unroll
        for (int i = tid; i < PATCH_F4; i += 256) {
            const int ppos = i >> 4;
            const int c4   = i & 15;
            const int py   = ppos / PW;
            const int px   = ppos - py * PW;
            const int y    = min(y_base + py, HH - 1);
            const int x    = min(x_base + px, WW - 1);
            patch[i] = *reinterpret_cast<const float4*>(src + ((size_t)y * WW + x) * CC + c4 * 4);
        }
    }
    __syncthreads();

    // ---- stage 1: y-combine into vrow (conflict-free lanes-over-channels) ----
    #pragma unroll
    for (int i = tid; i < VROW_F4; i += 256) {
        const int c4  = i & 15;
        const int pos = i >> 4;          // h*12 + x, 0..179
        const int h   = pos / PW;
        const int x   = pos - h * PW;
        const int ny  = s_yn[h];
        float4 acc = {0.f, 0.f, 0.f, 0.f};
        #pragma unroll
        for (int yi = 0; yi < 3; yi++) {
            if (yi < ny) {
                const float  wy = s_yw[h][yi];
                const float4 v  = patch[(s_yr[h][yi] * PW + x) * 16 + c4];
                acc.x = fmaf(wy, v.x, acc.x);
                acc.y = fmaf(wy, v.y, acc.y);
                acc.z = fmaf(wy, v.z, acc.z);
                acc.w = fmaf(wy, v.w, acc.w);
            }
        }
        vrow[VIDX(pos, c4)] = acc;
    }
    __syncthreads();

    if (tid >= OUT_HW * OUT_HW) return;

    // ---- stage 2: x-combine, thread = bin (coalesced output stores) ----
    const int h = tid / OUT_HW;
    const int w = tid - h * OUT_HW;

    const int nx = s_xn[w];
    int   pbase[3];
    int   psw[3];
    float wxs[3];
    #pragma unroll
    for (int xi = 0; xi < 3; xi++) {
        const int pos = h * PW + (xi < nx ? s_xc[w][xi] : 0);
        pbase[xi] = pos << 4;
        psw[xi]   = pos & 7;
        wxs[xi]   = xi < nx ? s_xw[w][xi] : 0.0f;
    }

    float* obase = out + ((size_t)n * CC + chunk * 64) * (OUT_HW * OUT_HW) + tid;

    #pragma unroll
    for (int cg = 0; cg < 4; cg++) {
        float4 a0 = {0.f, 0.f, 0.f, 0.f};
        float4 a1 = {0.f, 0.f, 0.f, 0.f};
        float4 a2 = {0.f, 0.f, 0.f, 0.f};
        float4 a3 = {0.f, 0.f, 0.f, 0.f};
        #pragma unroll
        for (int xi = 0; xi < 3; xi++) {
            if (xi < nx) {
                const float g  = wxs[xi];
                const int   bb = pbase[xi];
                const int   sw = psw[xi];
                float4 v;
                v = vrow[bb + ((cg * 4 + 0) ^ sw)];
                a0.x = fmaf(g, v.x, a0.x); a0.y = fmaf(g, v.y, a0.y);
                a0.z = fmaf(g, v.z, a0.z); a0.w = fmaf(g, v.w, a0.w);
                v = vrow[bb + ((cg * 4 + 1) ^ sw)];
                a1.x = fmaf(g, v.x, a1.x); a1.y = fmaf(g, v.y, a1.y);
                a1.z = fmaf(g, v.z, a1.z); a1.w = fmaf(g, v.w, a1.w);
                v = vrow[bb + ((cg * 4 + 2) ^ sw)];
                a2.x = fmaf(g, v.x, a2.x); a2.y = fmaf(g, v.y, a2.y);
                a2.z = fmaf(g, v.z, a2.z); a2.w = fmaf(g, v.w, a2.w);
                v = vrow[bb + ((cg * 4 + 3) ^ sw)];
                a3.x = fmaf(g, v.x, a3.x); a3.y = fmaf(g, v.y, a3.y);
                a3.z = fmaf(g, v.z, a3.z); a3.w = fmaf(g, v.w, a3.w);
            }
        }
        float* o = obase + (size_t)(cg * 16) * (OUT_HW * OUT_HW);
        const int S = OUT_HW * OUT_HW;
        o[0 * S]  = a0.x; o[1 * S]  = a0.y; o[2 * S]  = a0.z; o[3 * S]  = a0.w;
        o[4 * S]  = a1.x; o[5 * S]  = a1.y; o[6 * S]  = a1.z; o[7 * S]  = a1.w;
        o[8 * S]  = a2.x; o[9 * S]  = a2.y; o[10 * S] = a2.z; o[11 * S] = a2.w;
        o[12 * S] = a3.x; o[13 * S] = a3.y; o[14 * S] = a3.z; o[15 * S] = a3.w;
    }
}

// ---------------------------------------------------------------------------
extern "C" void kernel_launch(void* const* d_in, const int* in_sizes, int n_in,
                              void* d_out, int out_size) {
    const float* x     = (const float*)d_in[0];
    const float* boxes = (const float*)d_in[1];
    const int*   bidx  = (const int*)d_in[2];
    float*       out   = (float*)d_out;

    (void)in_sizes; (void)n_in; (void)out_size;

    cudaFuncSetAttribute(roi_kernel, cudaFuncAttributeMaxDynamicSharedMemorySize, SMEM_DYN);

    dim3 tb(32, 8);
    dim3 tg((HH * WW) / 32, CC / 32, 2);
    transpose_kernel<<<tg, tb>>>(x);

    dim3 rg(4, NBOX);
    roi_kernel<<<rg, 256, SMEM_DYN>>>(boxes, bidx, out);
}

// round 8
// speedup vs baseline: 3.9247x; 1.2091x over previous
#include <cuda_runtime.h>
#include <cuda_bf16.h>
#include <cstdint>

// ROIAlign, OUT=15x15, SCALE=1/16, SR=2
// x: [2,256,64,64] f32; boxes: [512,4] f32; batch_idx: [512] i32
// out: [512,256,15,15] f32
//
// v4: channels-last transpose -> per-(box,chunk) block, separable:
//   stage1: vrow[h][x][c] = sum_yi wy * g_xt[yabs][xabs][c]  (direct from L2/L1)
//   stage2: out[h][w][c]  = sum_xi wx * vrow[h][xc][c]
//   No patch smem buffer -> 46KB smem -> 4 blocks/SM (vs 2 at 83KB in v3).

#define HH 64
#define WW 64
#define CC 256
#define OUT_HW 15
#define NBOX 512
#define PW 12

#define VROW_F4  (OUT_HW * PW * 16)      // 2880 float4 = 46080 B
#define SMEM_DYN (VROW_F4 * 16)

// vrow index with XOR swizzle: pos in [0,180), c4 in [0,16)
#define VIDX(pos, c4) (((pos) << 4) + ((c4) ^ ((pos) & 7)))

// channels-last scratch: [2,64,64,256] f32 = 8MB
__device__ float g_xt[2 * HH * WW * CC];

// ---------------------------------------------------------------------------
// Transpose [B,C,H*W] -> [B,H*W,C] via 32x32 smem tiles
// ---------------------------------------------------------------------------
__global__ __launch_bounds__(256) void transpose_kernel(const float* __restrict__ x) {
    __shared__ float tile[32][33];
    int b   = blockIdx.z;
    int hw0 = blockIdx.x * 32;
    int c0  = blockIdx.y * 32;
    const float* src = x + ((size_t)b * CC) * (HH * WW);
    #pragma unroll
    for (int i = threadIdx.y; i < 32; i += 8)
        tile[i][threadIdx.x] = src[(size_t)(c0 + i) * (HH * WW) + hw0 + threadIdx.x];
    __syncthreads();
    float* dst = g_xt + (size_t)b * (HH * WW) * CC;
    #pragma unroll
    for (int i = threadIdx.y; i < 32; i += 8)
        dst[(size_t)(hw0 + i) * CC + c0 + threadIdx.x] = tile[threadIdx.x][i];
}

// ---------------------------------------------------------------------------
// Axis corner-list builder: dedup the <=4 bilinear corners of the 2
// subsamples into <=3 (clamped absolute index, weight) pairs. v = validity*0.5.
// ---------------------------------------------------------------------------
__device__ __forceinline__ void axis_bin(float a1, float bin, int bin_i,
                                         int size, int* o_idx, float* o_wt, int* o_n) {
    int   idx[3];
    float wt[3];
    int   cnt = 0;
    #pragma unroll
    for (int s = 0; s < 2; s++) {
        float p = a1 + ((float)(bin_i * 2 + s) + 0.5f) * 0.5f * bin;
        const float v = (p >= -1.0f && p <= (float)size) ? 0.5f : 0.0f;
        p = fminf(fmaxf(p, 0.0f), (float)(size - 1));
        int lo = (int)floorf(p);
        if (lo > size - 1) lo = size - 1;
        const int   hi = min(lo + 1, size - 1);
        const float f  = p - (float)lo;
        int   ci[2] = { lo, hi };
        float cw[2] = { (1.0f - f) * v, f * v };
        #pragma unroll
        for (int k = 0; k < 2; k++) {
            int m;
            for (m = 0; m < cnt; m++)
                if (idx[m] == ci[k]) { wt[m] += cw[k]; break; }
            if (m == cnt && cnt < 3) { idx[cnt] = ci[k]; wt[cnt] = cw[k]; cnt++; }
        }
    }
    *o_n = cnt;
    for (int m = 0; m < cnt; m++) { o_idx[m] = idx[m]; o_wt[m] = wt[m]; }
}

// ---------------------------------------------------------------------------
// ROI kernel: grid (4 chunk, 512 box), 256 threads.
// ---------------------------------------------------------------------------
__global__ __launch_bounds__(256) void roi_kernel(const float* __restrict__ boxes,
                                                  const int* __restrict__ batch_idx,
                                                  float* __restrict__ out) {
    extern __shared__ float4 vrow[];     // swizzled [pos 0..179][c4 0..15]

    __shared__ int    s_xn[OUT_HW];
    __shared__ int    s_xc[OUT_HW][3];   // relative x (0..11)
    __shared__ float  s_xw[OUT_HW][3];
    __shared__ int    s_yn[OUT_HW];
    __shared__ int    s_yoff[OUT_HW][3]; // absolute row offset into g_xt (floats)
    __shared__ float  s_yw[OUT_HW][3];

    const int chunk = blockIdx.x;
    const int n     = blockIdx.y;
    const int tid   = threadIdx.x;

    // ---- box geometry (broadcast loads) ----
    const float bx1 = boxes[n * 4 + 0] * 0.0625f;
    const float by1 = boxes[n * 4 + 1] * 0.0625f;
    const float bx2 = boxes[n * 4 + 2] * 0.0625f;
    const float by2 = boxes[n * 4 + 3] * 0.0625f;
    const float bin_w = fmaxf(bx2 - bx1, 1.0f) * (1.0f / OUT_HW);
    const float bin_h = fmaxf(by2 - by1, 1.0f) * (1.0f / OUT_HW);
    const int   b     = batch_idx[n];

    float p0x = fminf(fmaxf(bx1 + 0.25f * bin_w, 0.0f), (float)(WW - 1));
    const int x_base = (int)floorf(p0x);

    // ---- per-bin axis corner lists ----
    if (tid < OUT_HW) {
        int idx[3]; float wt[3]; int cnt;
        axis_bin(bx1, bin_w, tid, WW, idx, wt, &cnt);
        s_xn[tid] = cnt;
        for (int m = 0; m < cnt; m++) { s_xc[tid][m] = idx[m] - x_base; s_xw[tid][m] = wt[m]; }
    } else if (tid >= 32 && tid < 32 + OUT_HW) {
        const int h = tid - 32;
        int idx[3]; float wt[3]; int cnt;
        axis_bin(by1, bin_h, h, HH, idx, wt, &cnt);
        s_yn[h] = cnt;
        for (int m = 0; m < cnt; m++) {
            s_yoff[h][m] = (b * (HH * WW) + idx[m] * WW) * CC;
            s_yw[h][m]   = wt[m];
        }
    }
    __syncthreads();

    // ---- stage 1: y-combine directly from g_xt into vrow ----
    // lanes-over-channels: 16 consecutive lanes read one 256B row segment.
    {
        const float* srcc = g_xt + chunk * 64;
        #pragma unroll
        for (int i = tid; i < VROW_F4; i += 256) {
            const int c4  = i & 15;
            const int pos = i >> 4;          // h*12 + x, 0..179
            const int h   = pos / PW;
            const int x   = pos - h * PW;
            const int xabs = min(x_base + x, WW - 1);
            const int coff = xabs * CC + c4 * 4;
            const int ny   = s_yn[h];
            float4 acc = {0.f, 0.f, 0.f, 0.f};
            #pragma unroll
            for (int yi = 0; yi < 3; yi++) {
                if (yi < ny) {
                    const float  wy = s_yw[h][yi];
                    const float4 v  = *reinterpret_cast<const float4*>(srcc + s_yoff[h][yi] + coff);
                    acc.x = fmaf(wy, v.x, acc.x);
                    acc.y = fmaf(wy, v.y, acc.y);
                    acc.z = fmaf(wy, v.z, acc.z);
                    acc.w = fmaf(wy, v.w, acc.w);
                }
            }
            vrow[VIDX(pos, c4)] = acc;
        }
    }
    __syncthreads();

    if (tid >= OUT_HW * OUT_HW) return;

    // ---- stage 2: x-combine, thread = bin (coalesced output stores) ----
    const int h = tid / OUT_HW;
    const int w = tid - h * OUT_HW;

    const int nx = s_xn[w];
    int   pbase[3];
    int   psw[3];
    float wxs[3];
    #pragma unroll
    for (int xi = 0; xi < 3; xi++) {
        const int pos = h * PW + (xi < nx ? s_xc[w][xi] : 0);
        pbase[xi] = pos << 4;
        psw[xi]   = pos & 7;
        wxs[xi]   = xi < nx ? s_xw[w][xi] : 0.0f;
    }

    float* obase = out + ((size_t)n * CC + chunk * 64) * (OUT_HW * OUT_HW) + tid;

    #pragma unroll
    for (int cg = 0; cg < 4; cg++) {
        float4 a0 = {0.f, 0.f, 0.f, 0.f};
        float4 a1 = {0.f, 0.f, 0.f, 0.f};
        float4 a2 = {0.f, 0.f, 0.f, 0.f};
        float4 a3 = {0.f, 0.f, 0.f, 0.f};
        #pragma unroll
        for (int xi = 0; xi < 3; xi++) {
            if (xi < nx) {
                const float g  = wxs[xi];
                const int   bb = pbase[xi];
                const int   sw = psw[xi];
                float4 v;
                v = vrow[bb + ((cg * 4 + 0) ^ sw)];
                a0.x = fmaf(g, v.x, a0.x); a0.y = fmaf(g, v.y, a0.y);
                a0.z = fmaf(g, v.z, a0.z); a0.w = fmaf(g, v.w, a0.w);
                v = vrow[bb + ((cg * 4 + 1) ^ sw)];
                a1.x = fmaf(g, v.x, a1.x); a1.y = fmaf(g, v.y, a1.y);
                a1.z = fmaf(g, v.z, a1.z); a1.w = fmaf(g, v.w, a1.w);
                v = vrow[bb + ((cg * 4 + 2) ^ sw)];
                a2.x = fmaf(g, v.x, a2.x); a2.y = fmaf(g, v.y, a2.y);
                a2.z = fmaf(g, v.z, a2.z); a2.w = fmaf(g, v.w, a2.w);
                v = vrow[bb + ((cg * 4 + 3) ^ sw)];
                a3.x = fmaf(g, v.x, a3.x); a3.y = fmaf(g, v.y, a3.y);
                a3.z = fmaf(g, v.z, a3.z); a3.w = fmaf(g, v.w, a3.w);
            }
        }
        float* o = obase + (size_t)(cg * 16) * (OUT_HW * OUT_HW);
        const int S = OUT_HW * OUT_HW;
        o[0 * S]  = a0.x; o[1 * S]  = a0.y; o[2 * S]  = a0.z; o[3 * S]  = a0.w;
        o[4 * S]  = a1.x; o[5 * S]  = a1.y; o[6 * S]  = a1.z; o[7 * S]  = a1.w;
        o[8 * S]  = a2.x; o[9 * S]  = a2.y; o[10 * S] = a2.z; o[11 * S] = a2.w;
        o[12 * S] = a3.x; o[13 * S] = a3.y; o[14 * S] = a3.z; o[15 * S] = a3.w;
    }
}

// ---------------------------------------------------------------------------
extern "C" void kernel_launch(void* const* d_in, const int* in_sizes, int n_in,
                              void* d_out, int out_size) {
    const float* x     = (const float*)d_in[0];
    const float* boxes = (const float*)d_in[1];
    const int*   bidx  = (const int*)d_in[2];
    float*       out   = (float*)d_out;

    (void)in_sizes; (void)n_in; (void)out_size;

    cudaFuncSetAttribute(roi_kernel, cudaFuncAttributeMaxDynamicSharedMemorySize, SMEM_DYN);

    dim3 tb(32, 8);
    dim3 tg((HH * WW) / 32, CC / 32, 2);
    transpose_kernel<<<tg, tb>>>(x);

    dim3 rg(4, NBOX);
    roi_kernel<<<rg, 256, SMEM_DYN>>>(boxes, bidx, out);
}